// round 16
// baseline (speedup 1.0000x reference)
#include <cuda_runtime.h>
#include <cuda_bf16.h>
#include <math.h>
#include <stdint.h>

#define Bn 4
#define Sn 2048
#define En 1024
#define Hn 16
#define HDn 64
#define Tn (Bn*Sn)        // 8192 tokens
#define F1n (3*En)        // 3072

#define QSCALE 0.180336880436f   // 0.125 * log2(e): scores land in exp2 domain

// ---------------------------------------------------------------------------
// Scratch (static device globals — allocation-free per harness rules)
// ---------------------------------------------------------------------------
__device__ __nv_bfloat16 g_qh[(size_t)Bn*Hn*Sn*HDn];  // [b*H+h][s][d] (scaled)
__device__ __nv_bfloat16 g_ql[(size_t)Bn*Hn*Sn*HDn];
__device__ __nv_bfloat16 g_kh[(size_t)Bn*Hn*Sn*HDn];
__device__ __nv_bfloat16 g_kl[(size_t)Bn*Hn*Sn*HDn];
__device__ __nv_bfloat16 g_vh[(size_t)Bn*Hn*Sn*HDn];
__device__ __nv_bfloat16 g_vl[(size_t)Bn*Hn*Sn*HDn];
__device__ __nv_bfloat16 g_x_hi[(size_t)Tn*En];
__device__ __nv_bfloat16 g_x_lo[(size_t)Tn*En];
__device__ __nv_bfloat16 g_wq_hi[(size_t)F1n*En];
__device__ __nv_bfloat16 g_wq_lo[(size_t)F1n*En];
__device__ __nv_bfloat16 g_wp_hi[(size_t)En*En];
__device__ __nv_bfloat16 g_wp_lo[(size_t)En*En];
__device__ __nv_bfloat16 g_att_hi[(size_t)Tn*En];
__device__ __nv_bfloat16 g_att_lo[(size_t)Tn*En];

// ---------------------------------------------------------------------------
// Helpers (baseline PTX only — no 'a'-suffix arch features)
// ---------------------------------------------------------------------------
__device__ __forceinline__ uint32_t smem_u32(const void* p) {
    uint32_t a;
    asm("{ .reg .u64 t; cvta.to.shared.u64 t, %1; cvt.u32.u64 %0, t; }" : "=r"(a) : "l"(p));
    return a;
}

__device__ __forceinline__ void ldgsts16(uint32_t dst, const void* src) {
    asm volatile("cp.async.cg.shared.global [%0], [%1], 16;" :: "r"(dst), "l"(src));
}
__device__ __forceinline__ void ldgsts16_ca(uint32_t dst, const void* src) {
    asm volatile("cp.async.ca.shared.global [%0], [%1], 16;" :: "r"(dst), "l"(src));
}

#define LDSM_X4(r0, r1, r2, r3, addr) \
    asm volatile("ldmatrix.sync.aligned.m8n8.x4.shared.b16 {%0,%1,%2,%3}, [%4];" \
        : "=r"(r0), "=r"(r1), "=r"(r2), "=r"(r3) : "r"(addr))

#define LDSM_X4_T(r0, r1, r2, r3, addr) \
    asm volatile("ldmatrix.sync.aligned.m8n8.x4.trans.shared.b16 {%0,%1,%2,%3}, [%4];" \
        : "=r"(r0), "=r"(r1), "=r"(r2), "=r"(r3) : "r"(addr))

__device__ __forceinline__ void mma16816(float c[4], const uint32_t a[4],
                                         uint32_t b0, uint32_t b1) {
    asm volatile(
        "mma.sync.aligned.m16n8k16.row.col.f32.bf16.bf16.f32 "
        "{%0,%1,%2,%3}, {%4,%5,%6,%7}, {%8,%9}, {%0,%1,%2,%3};"
        : "+f"(c[0]), "+f"(c[1]), "+f"(c[2]), "+f"(c[3])
        : "r"(a[0]), "r"(a[1]), "r"(a[2]), "r"(a[3]), "r"(b0), "r"(b1));
}

__device__ __forceinline__ float ex2f(float x) {
    float r; asm("ex2.approx.ftz.f32 %0, %1;" : "=f"(r) : "f"(x)); return r;
}

__device__ __forceinline__ uint32_t pack_bf2(float a, float b) {
    __nv_bfloat162 h = __floats2bfloat162_rn(a, b);
    return *reinterpret_cast<uint32_t*>(&h);
}

// mbarrier primitives (sm_80/90 baseline PTX — no 'a'-gated features)
#define MBAR_INIT(mbar, cnt) \
    asm volatile("mbarrier.init.shared.b64 [%0], %1;" \
        :: "r"((uint32_t)(mbar)), "r"((uint32_t)(cnt)) : "memory")

#define MBAR_ARRIVE(mbar) \
    asm volatile("mbarrier.arrive.shared.b64 _, [%0];" \
        :: "r"((uint32_t)(mbar)) : "memory")

#define CP_ASYNC_ARRIVE(mbar) \
    asm volatile("cp.async.mbarrier.arrive.noinc.shared.b64 [%0];" \
        :: "r"((uint32_t)(mbar)) : "memory")

#define MBAR_WAIT(mbar, parity) do { \
    uint32_t _m = (uint32_t)(mbar); uint32_t _p = (uint32_t)(parity); uint32_t _ok; \
    asm volatile("{\n\t.reg .pred p;\n\t" \
        "mbarrier.try_wait.parity.acquire.cta.shared::cta.b64 p, [%1], %2;\n\t" \
        "selp.b32 %0, 1, 0, p;\n\t}" : "=r"(_ok) : "r"(_m), "r"(_p) : "memory"); \
    if (!_ok) { \
        asm volatile("{\n\t.reg .pred P1;\n\t" \
            "WL_%=:\n\t" \
            "mbarrier.try_wait.parity.acquire.cta.shared::cta.b64 P1, [%0], %1, 0x989680;\n\t" \
            "@P1 bra.uni WD_%=;\n\t" \
            "bra.uni WL_%=;\n\t" \
            "WD_%=:\n\t}" :: "r"(_m), "r"(_p) : "memory"); \
    } } while (0)

// GEMM smem swizzle: 64B rows, chunk XOR — 16B aligned, ldmatrix conflict-free
__device__ __forceinline__ uint32_t gsw(uint32_t row, uint32_t coloff) {
    return row*64u + (coloff ^ (((row >> 1) & 3u) << 4));
}
// Attention smem swizzle: 128B rows (pad-free), SW128-style XOR
__device__ __forceinline__ uint32_t asw(uint32_t row, uint32_t coloff) {
    return row*128u + (coloff ^ ((row & 7u) << 4));
}

// ---------------------------------------------------------------------------
// Kernel 0: fused fp32 -> (bf16 hi, bf16 lo) split for x, w_qkv, w_proj
// ---------------------------------------------------------------------------
#define N4_X   (Tn*En/4)
#define N4_WQ  (F1n*En/4)
#define N4_WP  (En*En/4)
#define N4_ALL (N4_X + N4_WQ + N4_WP)

__global__ __launch_bounds__(256) void split_all_kernel(
    const float4* __restrict__ x, const float4* __restrict__ wq,
    const float4* __restrict__ wp)
{
    int i = blockIdx.x * 256 + threadIdx.x;
    if (i >= N4_ALL) return;
    const float4* src;
    __nv_bfloat162 *hi, *lo;
    int j = i;
    if (j < N4_X) {
        src = x; hi = (__nv_bfloat162*)g_x_hi; lo = (__nv_bfloat162*)g_x_lo;
    } else if (j < N4_X + N4_WQ) {
        j -= N4_X;
        src = wq; hi = (__nv_bfloat162*)g_wq_hi; lo = (__nv_bfloat162*)g_wq_lo;
    } else {
        j -= N4_X + N4_WQ;
        src = wp; hi = (__nv_bfloat162*)g_wp_hi; lo = (__nv_bfloat162*)g_wp_lo;
    }
    float4 v = src[j];
    __nv_bfloat16 h0 = __float2bfloat16(v.x), h1 = __float2bfloat16(v.y);
    __nv_bfloat16 h2 = __float2bfloat16(v.z), h3 = __float2bfloat16(v.w);
    __nv_bfloat162 a; a.x = h0; a.y = h1;
    __nv_bfloat162 b; b.x = h2; b.y = h3;
    __nv_bfloat162 c; c.x = __float2bfloat16(v.x - __bfloat162float(h0));
    c.y = __float2bfloat16(v.y - __bfloat162float(h1));
    __nv_bfloat162 d; d.x = __float2bfloat16(v.z - __bfloat162float(h2));
    d.y = __float2bfloat16(v.w - __bfloat162float(h3));
    hi[2*j] = a; hi[2*j+1] = b;
    lo[2*j] = c; lo[2*j+1] = d;
}

// ---------------------------------------------------------------------------
// Persistent split-bf16 HMMA GEMM, continuous mbarrier pipeline.
// 296 CTAs (2/SM); each walks tiles cta, cta+296, ... The 3-slot ring never
// drains across tile boundaries: global stage s -> (tile s/NKI, ki s%NKI),
// slot s%3, parity (s/3)&1. Register-only epilogue overlaps next-tile loads.
// BM=128, BN=128, BK=32. 8 warps (2x4), each 64x32 tile.
//   mode 0: split C into bf16 hi/lo head-major q/k/v (q pre-scaled)
//   mode 1: C + bias -> out (fp32, row-major)
// ---------------------------------------------------------------------------
#define BMm 128
#define BNn 128
#define BKk 32
#define NKI (En/BKk)            // 32
#define OFF_ALO  8192           // 128*64
#define OFF_BHI 16384
#define OFF_BLO 24576
#define STAGEB  32768
#define GEMM_SMEM (3*STAGEB + 128)   // slots + 6 mbarriers
#define NPERSIST 296

__global__ __launch_bounds__(256, 2) void gemm_split_kernel(
    const __nv_bfloat16* __restrict__ Ahi, const __nv_bfloat16* __restrict__ Alo,
    const __nv_bfloat16* __restrict__ Bhi, const __nv_bfloat16* __restrict__ Blo,
    float* __restrict__ outp, const float* __restrict__ bias, int mode,
    int gx, int NT)
{
    extern __shared__ char dsm[];
    const uint32_t sb = smem_u32(dsm);
    const uint32_t FULLB  = sb + 3*STAGEB;       // 3 x 8B
    const uint32_t EMPTYB = sb + 3*STAGEB + 24;  // 3 x 8B
    const int tid = threadIdx.x;
    const int wid = tid >> 5, lane = tid & 31;
    const int wy = wid & 1, wx = wid >> 1;       // warp tile: (wy*64, wx*32)
    const int myc = blockIdx.x;
    const int ncta = gridDim.x;

    if (tid == 0) {
        #pragma unroll
        for (int s = 0; s < 3; s++) {
            MBAR_INIT(FULLB  + s*8, 256);
            MBAR_INIT(EMPTYB + s*8, 256);
        }
    }
    __syncthreads();   // only block-wide barrier in the kernel

    const int nmy = (myc < NT) ? ((NT - myc + ncta - 1) / ncta) : 0;
    const int total = nmy * NKI;
    if (total == 0) return;

    // stage s -> load into slot s%3 (tile coords derived from s)
    #define LOAD_STAGE_P(s) do {                                              \
        int sj_ = (s) / NKI, ski_ = (s) - sj_*NKI;                            \
        int tile_ = myc + sj_*ncta;                                           \
        int st0_ = (tile_ / gx) * BMm;                                        \
        int sf0_ = (tile_ - (tile_ / gx)*gx) * BNn;                           \
        uint32_t base_ = sb + (uint32_t)((s) % 3)*STAGEB;                     \
        int kofs_ = ski_*BKk;                                                 \
        _Pragma("unroll")                                                     \
        for (int jj = 0; jj < 2; jj++) {                                      \
            int c_ = tid + jj*256;                                            \
            uint32_t row_ = (uint32_t)(c_ >> 2), ch_ = (uint32_t)(c_ & 3);    \
            uint32_t so_ = gsw(row_, ch_*16u);                                \
            size_t ga_ = (size_t)(st0_ + (int)row_)*En + kofs_ + (int)ch_*8;  \
            size_t gb_ = (size_t)(sf0_ + (int)row_)*En + kofs_ + (int)ch_*8;  \
            ldgsts16_ca(base_ + so_,           Ahi + ga_);                    \
            ldgsts16_ca(base_ + OFF_ALO + so_, Alo + ga_);                    \
            ldgsts16(base_ + OFF_BHI + so_, Bhi + gb_);                       \
            ldgsts16(base_ + OFF_BLO + so_, Blo + gb_);                       \
        }                                                                     \
    } while (0)

    float acc[4][4][4] = {};   // [mi][nj][frag]

    // prologue: stages 0,1 (virgin slots — no empty wait)
    LOAD_STAGE_P(0);
    CP_ASYNC_ARRIVE(FULLB + 0);
    if (total > 1) {
        LOAD_STAGE_P(1);
        CP_ASYNC_ARRIVE(FULLB + 8);
    }

    for (int s = 0; s < total; s++) {
        const int slot = s % 3;
        MBAR_WAIT(FULLB + slot*8, (uint32_t)((s/3) & 1));

        const uint32_t base = sb + (uint32_t)slot*STAGEB;
        const uint32_t lrow = lane & 15;
        const uint32_t lcol = (lane >> 4) << 4;

        #pragma unroll
        for (int kk = 0; kk < 2; kk++) {
            const uint32_t coff = (uint32_t)kk*32 + lcol;
            uint32_t ah[4][4], al[4][4];
            #pragma unroll
            for (int mi = 0; mi < 4; mi++) {
                uint32_t r = (uint32_t)(wy*64 + mi*16) + lrow;
                uint32_t addr = base + gsw(r, coff);
                LDSM_X4(ah[mi][0], ah[mi][1], ah[mi][2], ah[mi][3], addr);
                LDSM_X4(al[mi][0], al[mi][1], al[mi][2], al[mi][3], addr + OFF_ALO);
            }
            uint32_t bh[4][2], bl[4][2];
            #pragma unroll
            for (int pj = 0; pj < 2; pj++) {
                uint32_t r = (uint32_t)(wx*32 + pj*16) + lrow;
                uint32_t addr = base + OFF_BHI + gsw(r, coff);
                uint32_t r0, r1, r2, r3;
                LDSM_X4(r0, r1, r2, r3, addr);
                bh[2*pj][0] = r0; bh[2*pj+1][0] = r1;
                bh[2*pj][1] = r2; bh[2*pj+1][1] = r3;
                LDSM_X4(r0, r1, r2, r3, addr + (OFF_BLO - OFF_BHI));
                bl[2*pj][0] = r0; bl[2*pj+1][0] = r1;
                bl[2*pj][1] = r2; bl[2*pj+1][1] = r3;
            }
            if (kk == 1) MBAR_ARRIVE(EMPTYB + slot*8);  // all reads of slot issued
            #pragma unroll
            for (int mi = 0; mi < 4; mi++)
                #pragma unroll
                for (int nj = 0; nj < 4; nj++)
                    mma16816(acc[mi][nj], ah[mi], bh[nj][0], bh[nj][1]);
            #pragma unroll
            for (int mi = 0; mi < 4; mi++)
                #pragma unroll
                for (int nj = 0; nj < 4; nj++)
                    mma16816(acc[mi][nj], ah[mi], bl[nj][0], bl[nj][1]);
            #pragma unroll
            for (int mi = 0; mi < 4; mi++)
                #pragma unroll
                for (int nj = 0; nj < 4; nj++)
                    mma16816(acc[mi][nj], al[mi], bh[nj][0], bh[nj][1]);
        }

        // produce stage s+2 (may belong to the next tile — pipeline never drains)
        if (s + 2 < total) {
            int s2 = s + 2;
            int ls = s2 % 3;
            int m = s2 / 3;
            if (m >= 1) MBAR_WAIT(EMPTYB + ls*8, (uint32_t)((m - 1) & 1));
            LOAD_STAGE_P(s2);
            CP_ASYNC_ARRIVE(FULLB + ls*8);
        }

        // tile finished -> epilogue (register-only; overlaps next-tile cp.async)
        if ((s % NKI) == NKI - 1) {
            int tile = myc + (s / NKI) * ncta;
            int t0 = (tile / gx) * BMm;
            int f0 = (tile - (tile / gx)*gx) * BNn;
            const int mrow = lane >> 2;
            const int ncol = (lane & 3) * 2;
            #pragma unroll
            for (int mi = 0; mi < 4; mi++) {
                #pragma unroll
                for (int half = 0; half < 2; half++) {
                    int t = t0 + wy*64 + mi*16 + mrow + half*8;
                    #pragma unroll
                    for (int nj = 0; nj < 4; nj++) {
                        int f = f0 + wx*32 + nj*8 + ncol;
                        float v0 = acc[mi][nj][half*2 + 0];
                        float v1 = acc[mi][nj][half*2 + 1];
                        if (mode == 0) {
                            int bidx = t >> 11, sidx = t & 2047;
                            int hh = f / 192;
                            int c = f - hh*192;
                            int kind = c >> 6, d = c & 63;
                            if (kind == 0) { v0 *= QSCALE; v1 *= QSCALE; }
                            __nv_bfloat16* hp = (kind == 0) ? g_qh : ((kind == 1) ? g_kh : g_vh);
                            __nv_bfloat16* lp = (kind == 0) ? g_ql : ((kind == 1) ? g_kl : g_vl);
                            size_t idx = (((size_t)(bidx*Hn + hh))*Sn + sidx)*HDn + d;
                            __nv_bfloat162 h2 = __floats2bfloat162_rn(v0, v1);
                            __nv_bfloat162 l2 = __floats2bfloat162_rn(
                                v0 - __bfloat162float(h2.x), v1 - __bfloat162float(h2.y));
                            *(__nv_bfloat162*)(hp + idx) = h2;
                            *(__nv_bfloat162*)(lp + idx) = l2;
                        } else {
                            float2* p = (float2*)&outp[(size_t)t*En + f];
                            *p = make_float2(v0 + bias[f], v1 + bias[f + 1]);
                        }
                    }
                }
            }
            #pragma unroll
            for (int mi = 0; mi < 4; mi++)
                #pragma unroll
                for (int nj = 0; nj < 4; nj++)
                    #pragma unroll
                    for (int q = 0; q < 4; q++)
                        acc[mi][nj][q] = 0.f;
        }
    }
}

// ---------------------------------------------------------------------------
// Kernel 2: causal flash attention (R15-proven), split-bf16 HMMA.
// 64 q-rows per CTA (4 warps, 128 threads), 3-slot swizzled KV ring,
// barrier-free mainloop, 2 CTAs/SM, qt longest-first.
// ---------------------------------------------------------------------------
#define A_QH 0
#define A_QL 8192               // 64 rows x 128B
#define A_ST0 16384
#define A_KH 0
#define A_KL 8192
#define A_VH 16384
#define A_VL 24576
#define A_STAGE 32768
#define ATTN_SMEM (A_ST0 + 3*A_STAGE + 128)   // 114816 (+6 mbarriers)

__global__ __launch_bounds__(128, 2) void attn_mma_kernel()
{
    extern __shared__ char dsm[];
    const uint32_t sb = smem_u32(dsm);
    const uint32_t FULLB  = sb + A_ST0 + 3*A_STAGE;       // 3 x 8B
    const uint32_t EMPTYB = sb + A_ST0 + 3*A_STAGE + 24;  // 3 x 8B
    const int tid = threadIdx.x;
    const int wid = tid >> 5, lane = tid & 31;   // wid 0..3
    const int qt = gridDim.x - 1 - blockIdx.x;   // longest-first (qt 0..31)
    const int bh = blockIdx.y;
    const int q0 = qt * 64;
    const size_t gbase = (size_t)bh * Sn * HDn;
    const int nk = qt + 1;                       // kv tiles (>=1)

    if (tid == 0) {
        #pragma unroll
        for (int s = 0; s < 3; s++) {
            MBAR_INIT(FULLB  + s*8, 128);
            MBAR_INIT(EMPTYB + s*8, 128);
        }
    }
    __syncthreads();   // only block barrier (covers mbarrier init)

    #define LOAD_KV(kt_, s_) do {                                             \
        uint32_t st_ = sb + A_ST0 + (uint32_t)(s_)*A_STAGE;                   \
        int kv_ = (kt_)*64;                                                   \
        _Pragma("unroll")                                                     \
        for (int j_ = 0; j_ < 4; j_++) {                                      \
            int c_ = tid + j_*128;                                            \
            uint32_t row_ = (uint32_t)(c_ >> 3), ch_ = (uint32_t)(c_ & 7);    \
            uint32_t so_ = asw(row_, ch_*16u);                                \
            size_t go_ = gbase + (size_t)(kv_ + (int)row_)*HDn + (int)ch_*8;  \
            ldgsts16(st_ + A_KH + so_, g_kh + go_);                           \
            ldgsts16(st_ + A_KL + so_, g_kl + go_);                           \
            ldgsts16(st_ + A_VH + so_, g_vh + go_);                           \
            ldgsts16(st_ + A_VL + so_, g_vl + go_);                           \
        } } while (0)

    // prologue: Q + KV0 tracked by FULL0 (noinc covers Q loads too); KV1 -> FULL1
    #pragma unroll
    for (int j = 0; j < 4; j++) {
        int c = tid + j*128;
        uint32_t row = (uint32_t)(c >> 3), ch = (uint32_t)(c & 7);
        uint32_t so = asw(row, ch*16u);
        size_t go = gbase + (size_t)(q0 + (int)row)*HDn + (int)ch*8;
        ldgsts16(sb + A_QH + so, g_qh + go);
        ldgsts16(sb + A_QL + so, g_ql + go);
    }
    LOAD_KV(0, 0);
    CP_ASYNC_ARRIVE(FULLB + 0);
    if (nk > 1) {
        LOAD_KV(1, 1);
        CP_ASYNC_ARRIVE(FULLB + 8);
    }

    // wait KV0 (and Q) resident, then grab Q fragments
    MBAR_WAIT(FULLB + 0, 0u);
    uint32_t qh_[4][4], ql_[4][4];
    {
        uint32_t r_ = (uint32_t)(wid*16 + (lane & 15));
        uint32_t cb = (uint32_t)((lane >> 4) << 4);
        #pragma unroll
        for (int kk = 0; kk < 4; kk++) {
            uint32_t addr = sb + A_QH + asw(r_, (uint32_t)kk*32 + cb);
            LDSM_X4(qh_[kk][0], qh_[kk][1], qh_[kk][2], qh_[kk][3], addr);
            LDSM_X4(ql_[kk][0], ql_[kk][1], ql_[kk][2], ql_[kk][3], addr + (A_QL - A_QH));
        }
    }

    float m0 = -INFINITY, m1 = -INFINITY, l0 = 0.f, l1 = 0.f;
    float acc[8][4] = {};

    for (int kt = 0; kt < nk; kt++) {
        const int slot = kt % 3;
        if (kt > 0) MBAR_WAIT(FULLB + slot*8, (uint32_t)((kt/3) & 1));

        const uint32_t st = sb + A_ST0 + (uint32_t)slot*A_STAGE;
        const int kv0 = kt * 64;

        // ---- S = Q @ K^T (3-term split, term-outer) ----
        float s[8][4] = {};
        {
            uint32_t r_ = (uint32_t)(lane & 15);
            uint32_t cb = (uint32_t)((lane >> 4) << 4);
            #pragma unroll
            for (int kk = 0; kk < 4; kk++) {
                uint32_t kh[8][2], kl[8][2];
                #pragma unroll
                for (int pj = 0; pj < 4; pj++) {
                    uint32_t addr = st + A_KH
                                  + asw((uint32_t)(pj*16) + r_, (uint32_t)kk*32 + cb);
                    uint32_t r0, r1, r2, r3;
                    LDSM_X4(r0, r1, r2, r3, addr);
                    kh[2*pj][0]=r0; kh[2*pj][1]=r2; kh[2*pj+1][0]=r1; kh[2*pj+1][1]=r3;
                    LDSM_X4(r0, r1, r2, r3, addr + (A_KL - A_KH));
                    kl[2*pj][0]=r0; kl[2*pj][1]=r2; kl[2*pj+1][0]=r1; kl[2*pj+1][1]=r3;
                }
                #pragma unroll
                for (int nj = 0; nj < 8; nj++)
                    mma16816(s[nj], qh_[kk], kh[nj][0], kh[nj][1]);
                #pragma unroll
                for (int nj = 0; nj < 8; nj++)
                    mma16816(s[nj], qh_[kk], kl[nj][0], kl[nj][1]);
                #pragma unroll
                for (int nj = 0; nj < 8; nj++)
                    mma16816(s[nj], ql_[kk], kh[nj][0], kh[nj][1]);
            }
        }

        // ---- causal mask (only diagonal tile needs it: kt == qt) ----
        const int rbase = q0 + wid*16 + (lane >> 2);
        if (kv0 + 63 > q0 + wid*16) {
            #pragma unroll
            for (int nj = 0; nj < 8; nj++)
                #pragma unroll
                for (int i = 0; i < 4; i++) {
                    int col = kv0 + nj*8 + (lane & 3)*2 + (i & 1);
                    int row = rbase + (i >> 1)*8;
                    if (col > row) s[nj][i] = -INFINITY;
                }
        }

        // ---- online softmax (exp2 domain) ----
        float mx0 = -INFINITY, mx1 = -INFINITY;
        #pragma unroll
        for (int nj = 0; nj < 8; nj++) {
            mx0 = fmaxf(mx0, fmaxf(s[nj][0], s[nj][1]));
            mx1 = fmaxf(mx1, fmaxf(s[nj][2], s[nj][3]));
        }
        mx0 = fmaxf(mx0, __shfl_xor_sync(0xffffffffu, mx0, 1));
        mx0 = fmaxf(mx0, __shfl_xor_sync(0xffffffffu, mx0, 2));
        mx1 = fmaxf(mx1, __shfl_xor_sync(0xffffffffu, mx1, 1));
        mx1 = fmaxf(mx1, __shfl_xor_sync(0xffffffffu, mx1, 2));
        float mn0 = fmaxf(m0, mx0), mn1 = fmaxf(m1, mx1);
        float al0 = ex2f(m0 - mn0), al1 = ex2f(m1 - mn1);
        m0 = mn0; m1 = mn1;
        float rs0 = 0.f, rs1 = 0.f;
        #pragma unroll
        for (int nj = 0; nj < 8; nj++) {
            float p0 = ex2f(s[nj][0] - mn0), p1 = ex2f(s[nj][1] - mn0);
            float p2 = ex2f(s[nj][2] - mn1), p3 = ex2f(s[nj][3] - mn1);
            s[nj][0] = p0; s[nj][1] = p1; s[nj][2] = p2; s[nj][3] = p3;
            rs0 += p0 + p1; rs1 += p2 + p3;
        }
        rs0 += __shfl_xor_sync(0xffffffffu, rs0, 1);
        rs0 += __shfl_xor_sync(0xffffffffu, rs0, 2);
        rs1 += __shfl_xor_sync(0xffffffffu, rs1, 1);
        rs1 += __shfl_xor_sync(0xffffffffu, rs1, 2);
        l0 = l0*al0 + rs0;
        l1 = l1*al1 + rs1;
        #pragma unroll
        for (int nj = 0; nj < 8; nj++) {
            acc[nj][0] *= al0; acc[nj][1] *= al0;
            acc[nj][2] *= al1; acc[nj][3] *= al1;
        }

        // ---- O += P @ V (3-term split, term-outer; V via ldmatrix.trans) ----
        {
            uint32_t rr = (uint32_t)(((lane >> 4) << 3) + (lane & 7));
            uint32_t cb = (uint32_t)(((lane >> 3) & 1) << 4);
            #pragma unroll
            for (int kk2 = 0; kk2 < 4; kk2++) {
                uint32_t pah[4], pal[4];
                #pragma unroll
                for (int tp = 0; tp < 2; tp++) {
                    int t_ = 2*kk2 + tp;
                    float p0 = s[t_][0], p1 = s[t_][1], p2 = s[t_][2], p3 = s[t_][3];
                    __nv_bfloat162 h01 = __floats2bfloat162_rn(p0, p1);
                    __nv_bfloat162 h23 = __floats2bfloat162_rn(p2, p3);
                    pah[2*tp+0] = *reinterpret_cast<uint32_t*>(&h01);
                    pah[2*tp+1] = *reinterpret_cast<uint32_t*>(&h23);
                    pal[2*tp+0] = pack_bf2(p0 - __bfloat162float(h01.x),
                                           p1 - __bfloat162float(h01.y));
                    pal[2*tp+1] = pack_bf2(p2 - __bfloat162float(h23.x),
                                           p3 - __bfloat162float(h23.y));
                }
                uint32_t bvh[8][2], bvl[8][2];
                #pragma unroll
                for (int dj = 0; dj < 4; dj++) {
                    uint32_t addr = st + A_VH
                                  + asw((uint32_t)(kk2*16) + rr, (uint32_t)dj*32 + cb);
                    uint32_t r0, r1, r2, r3;
                    LDSM_X4_T(r0, r1, r2, r3, addr);
                    bvh[2*dj][0]=r0; bvh[2*dj][1]=r2; bvh[2*dj+1][0]=r1; bvh[2*dj+1][1]=r3;
                    LDSM_X4_T(r0, r1, r2, r3, addr + (A_VL - A_VH));
                    bvl[2*dj][0]=r0; bvl[2*dj][1]=r2; bvl[2*dj+1][0]=r1; bvl[2*dj+1][1]=r3;
                }
                #pragma unroll
                for (int nj = 0; nj < 8; nj++)
                    mma16816(acc[nj], pah, bvh[nj][0], bvh[nj][1]);
                #pragma unroll
                for (int nj = 0; nj < 8; nj++)
                    mma16816(acc[nj], pah, bvl[nj][0], bvl[nj][1]);
                #pragma unroll
                for (int nj = 0; nj < 8; nj++)
                    mma16816(acc[nj], pal, bvh[nj][0], bvh[nj][1]);
            }
        }

        // all reads of this slot issued -> release
        MBAR_ARRIVE(EMPTYB + slot*8);

        // produce kt+2 into slot (kt+2)%3
        if (kt + 2 < nk) {
            int stg = kt + 2;
            int ls = stg % 3;
            int m = stg / 3;
            if (m >= 1) MBAR_WAIT(EMPTYB + ls*8, (uint32_t)((m - 1) & 1));
            LOAD_KV(stg, ls);
            CP_ASYNC_ARRIVE(FULLB + ls*8);
        }
    }

    // ---- epilogue: normalize, write bf16 hi/lo for proj GEMM ----
    float inv0 = 1.f / l0, inv1 = 1.f / l1;
    const int b = bh >> 4, h = bh & 15;
    const int r0_ = q0 + wid*16 + (lane >> 2);
    #pragma unroll
    for (int nj = 0; nj < 8; nj++) {
        int d = nj*8 + (lane & 3)*2;
        size_t i0 = (size_t)(b*Sn + r0_)*En + h*HDn + d;
        size_t i1 = i0 + (size_t)8*En;
        float o0 = acc[nj][0]*inv0, o1 = acc[nj][1]*inv0;
        float o2 = acc[nj][2]*inv1, o3 = acc[nj][3]*inv1;
        __nv_bfloat162 h01 = __floats2bfloat162_rn(o0, o1);
        __nv_bfloat162 l01 = __floats2bfloat162_rn(o0 - __bfloat162float(h01.x),
                                                   o1 - __bfloat162float(h01.y));
        __nv_bfloat162 h23 = __floats2bfloat162_rn(o2, o3);
        __nv_bfloat162 l23 = __floats2bfloat162_rn(o2 - __bfloat162float(h23.x),
                                                   o3 - __bfloat162float(h23.y));
        *(__nv_bfloat162*)(g_att_hi + i0) = h01;
        *(__nv_bfloat162*)(g_att_lo + i0) = l01;
        *(__nv_bfloat162*)(g_att_hi + i1) = h23;
        *(__nv_bfloat162*)(g_att_lo + i1) = l23;
    }
}

// ---------------------------------------------------------------------------
extern "C" void kernel_launch(void* const* d_in, const int* in_sizes, int n_in,
                              void* d_out, int out_size)
{
    const float* x      = (const float*)d_in[0];
    const float* w_qkv  = (const float*)d_in[1];
    const float* w_proj = (const float*)d_in[2];
    const float* b_proj = (const float*)d_in[3];
    float* out = (float*)d_out;

    cudaFuncSetAttribute(gemm_split_kernel,
                         cudaFuncAttributeMaxDynamicSharedMemorySize, GEMM_SMEM);
    cudaFuncSetAttribute(attn_mma_kernel,
                         cudaFuncAttributeMaxDynamicSharedMemorySize, ATTN_SMEM);

    __nv_bfloat16 *xhi, *xlo, *wqhi, *wqlo, *wphi, *wplo, *athi, *atlo;
    cudaGetSymbolAddress((void**)&xhi,  g_x_hi);
    cudaGetSymbolAddress((void**)&xlo,  g_x_lo);
    cudaGetSymbolAddress((void**)&wqhi, g_wq_hi);
    cudaGetSymbolAddress((void**)&wqlo, g_wq_lo);
    cudaGetSymbolAddress((void**)&wphi, g_wp_hi);
    cudaGetSymbolAddress((void**)&wplo, g_wp_lo);
    cudaGetSymbolAddress((void**)&athi, g_att_hi);
    cudaGetSymbolAddress((void**)&atlo, g_att_lo);

    // fused fp32 -> bf16 hi/lo split (x, w_qkv, w_proj in one launch)
    split_all_kernel<<<(N4_ALL + 255)/256, 256>>>(
        (const float4*)x, (const float4*)w_qkv, (const float4*)w_proj);

    // QKV GEMM (persistent, continuous mbarrier pipeline): 24x64 = 1536 tiles
    gemm_split_kernel<<<NPERSIST, 256, GEMM_SMEM>>>(
        xhi, xlo, wqhi, wqlo, nullptr, nullptr, 0, F1n/BNn, (F1n/BNn)*(Tn/BMm));

    // causal flash attention (split-bf16 HMMA, 3-slot mbarrier KV ring)
    attn_mma_kernel<<<dim3(Sn/64, Bn*Hn), 128, ATTN_SMEM>>>();

    // output projection (persistent) + bias: 8x64 = 512 tiles
    gemm_split_kernel<<<NPERSIST, 256, GEMM_SMEM>>>(
        athi, atlo, wphi, wplo, out, b_proj, 1, En/BNn, (En/BNn)*(Tn/BMm));
}

// round 17
// speedup vs baseline: 1.0401x; 1.0401x over previous
#include <cuda_runtime.h>
#include <cuda_bf16.h>
#include <math.h>
#include <stdint.h>

#define Bn 4
#define Sn 2048
#define En 1024
#define Hn 16
#define HDn 64
#define Tn (Bn*Sn)        // 8192 tokens
#define F1n (3*En)        // 3072

#define QSCALE 0.180336880436f   // 0.125 * log2(e): scores land in exp2 domain

// ---------------------------------------------------------------------------
// Scratch (static device globals — allocation-free per harness rules)
// ---------------------------------------------------------------------------
__device__ __nv_bfloat16 g_qh[(size_t)Bn*Hn*Sn*HDn];  // [b*H+h][s][d] (scaled)
__device__ __nv_bfloat16 g_ql[(size_t)Bn*Hn*Sn*HDn];
__device__ __nv_bfloat16 g_kh[(size_t)Bn*Hn*Sn*HDn];
__device__ __nv_bfloat16 g_kl[(size_t)Bn*Hn*Sn*HDn];
__device__ __nv_bfloat16 g_vh[(size_t)Bn*Hn*Sn*HDn];
__device__ __nv_bfloat16 g_vl[(size_t)Bn*Hn*Sn*HDn];
__device__ __nv_bfloat16 g_x_hi[(size_t)Tn*En];
__device__ __nv_bfloat16 g_x_lo[(size_t)Tn*En];
__device__ __nv_bfloat16 g_wq_hi[(size_t)F1n*En];
__device__ __nv_bfloat16 g_wq_lo[(size_t)F1n*En];
__device__ __nv_bfloat16 g_wp_hi[(size_t)En*En];
__device__ __nv_bfloat16 g_wp_lo[(size_t)En*En];
__device__ __nv_bfloat16 g_att_hi[(size_t)Tn*En];
__device__ __nv_bfloat16 g_att_lo[(size_t)Tn*En];

// ---------------------------------------------------------------------------
// Helpers (baseline PTX only — no 'a'-suffix arch features)
// ---------------------------------------------------------------------------
__device__ __forceinline__ uint32_t smem_u32(const void* p) {
    uint32_t a;
    asm("{ .reg .u64 t; cvta.to.shared.u64 t, %1; cvt.u32.u64 %0, t; }" : "=r"(a) : "l"(p));
    return a;
}

__device__ __forceinline__ void ldgsts16(uint32_t dst, const void* src) {
    asm volatile("cp.async.cg.shared.global [%0], [%1], 16;" :: "r"(dst), "l"(src));
}
__device__ __forceinline__ void ldgsts16_ca(uint32_t dst, const void* src) {
    asm volatile("cp.async.ca.shared.global [%0], [%1], 16;" :: "r"(dst), "l"(src));
}

#define LDSM_X4(r0, r1, r2, r3, addr) \
    asm volatile("ldmatrix.sync.aligned.m8n8.x4.shared.b16 {%0,%1,%2,%3}, [%4];" \
        : "=r"(r0), "=r"(r1), "=r"(r2), "=r"(r3) : "r"(addr))

#define LDSM_X4_T(r0, r1, r2, r3, addr) \
    asm volatile("ldmatrix.sync.aligned.m8n8.x4.trans.shared.b16 {%0,%1,%2,%3}, [%4];" \
        : "=r"(r0), "=r"(r1), "=r"(r2), "=r"(r3) : "r"(addr))

__device__ __forceinline__ void mma16816(float c[4], const uint32_t a[4],
                                         uint32_t b0, uint32_t b1) {
    asm volatile(
        "mma.sync.aligned.m16n8k16.row.col.f32.bf16.bf16.f32 "
        "{%0,%1,%2,%3}, {%4,%5,%6,%7}, {%8,%9}, {%0,%1,%2,%3};"
        : "+f"(c[0]), "+f"(c[1]), "+f"(c[2]), "+f"(c[3])
        : "r"(a[0]), "r"(a[1]), "r"(a[2]), "r"(a[3]), "r"(b0), "r"(b1));
}

__device__ __forceinline__ float ex2f(float x) {
    float r; asm("ex2.approx.ftz.f32 %0, %1;" : "=f"(r) : "f"(x)); return r;
}

__device__ __forceinline__ uint32_t pack_bf2(float a, float b) {
    __nv_bfloat162 h = __floats2bfloat162_rn(a, b);
    return *reinterpret_cast<uint32_t*>(&h);
}

// mbarrier primitives (sm_80/90 baseline PTX — no 'a'-gated features)
#define MBAR_INIT(mbar, cnt) \
    asm volatile("mbarrier.init.shared.b64 [%0], %1;" \
        :: "r"((uint32_t)(mbar)), "r"((uint32_t)(cnt)) : "memory")

#define MBAR_ARRIVE(mbar) \
    asm volatile("mbarrier.arrive.shared.b64 _, [%0];" \
        :: "r"((uint32_t)(mbar)) : "memory")

#define CP_ASYNC_ARRIVE(mbar) \
    asm volatile("cp.async.mbarrier.arrive.noinc.shared.b64 [%0];" \
        :: "r"((uint32_t)(mbar)) : "memory")

#define MBAR_WAIT(mbar, parity) do { \
    uint32_t _m = (uint32_t)(mbar); uint32_t _p = (uint32_t)(parity); uint32_t _ok; \
    asm volatile("{\n\t.reg .pred p;\n\t" \
        "mbarrier.try_wait.parity.acquire.cta.shared::cta.b64 p, [%1], %2;\n\t" \
        "selp.b32 %0, 1, 0, p;\n\t}" : "=r"(_ok) : "r"(_m), "r"(_p) : "memory"); \
    if (!_ok) { \
        asm volatile("{\n\t.reg .pred P1;\n\t" \
            "WL_%=:\n\t" \
            "mbarrier.try_wait.parity.acquire.cta.shared::cta.b64 P1, [%0], %1, 0x989680;\n\t" \
            "@P1 bra.uni WD_%=;\n\t" \
            "bra.uni WL_%=;\n\t" \
            "WD_%=:\n\t}" :: "r"(_m), "r"(_p) : "memory"); \
    } } while (0)

// GEMM smem swizzle: 64B rows, chunk XOR — 16B aligned, ldmatrix conflict-free
__device__ __forceinline__ uint32_t gsw(uint32_t row, uint32_t coloff) {
    return row*64u + (coloff ^ (((row >> 1) & 3u) << 4));
}
// Attention smem swizzle: 128B rows (pad-free), SW128-style XOR
__device__ __forceinline__ uint32_t asw(uint32_t row, uint32_t coloff) {
    return row*128u + (coloff ^ ((row & 7u) << 4));
}

// ---------------------------------------------------------------------------
// Kernel 0: fused fp32 -> (bf16 hi, bf16 lo) split for x, w_qkv, w_proj.
// Each thread: 8 floats (2x float4 loads) -> one 16B hi store + one 16B lo.
// ---------------------------------------------------------------------------
#define N8_X   (Tn*En/8)
#define N8_WQ  (F1n*En/8)
#define N8_WP  (En*En/8)
#define N8_ALL (N8_X + N8_WQ + N8_WP)

__global__ __launch_bounds__(256) void split_all_kernel(
    const float4* __restrict__ x, const float4* __restrict__ wq,
    const float4* __restrict__ wp)
{
    int i = blockIdx.x * 256 + threadIdx.x;
    if (i >= N8_ALL) return;
    const float4* src;
    uint4 *hi, *lo;
    int j = i;
    if (j < N8_X) {
        src = x; hi = (uint4*)g_x_hi; lo = (uint4*)g_x_lo;
    } else if (j < N8_X + N8_WQ) {
        j -= N8_X;
        src = wq; hi = (uint4*)g_wq_hi; lo = (uint4*)g_wq_lo;
    } else {
        j -= N8_X + N8_WQ;
        src = wp; hi = (uint4*)g_wp_hi; lo = (uint4*)g_wp_lo;
    }
    float4 a = src[2*j], b = src[2*j + 1];
    float v[8] = {a.x, a.y, a.z, a.w, b.x, b.y, b.z, b.w};
    uint32_t hw[4], lw[4];
    #pragma unroll
    for (int q = 0; q < 4; q++) {
        __nv_bfloat162 h2 = __floats2bfloat162_rn(v[2*q], v[2*q + 1]);
        hw[q] = *reinterpret_cast<uint32_t*>(&h2);
        __nv_bfloat162 l2 = __floats2bfloat162_rn(
            v[2*q]     - __bfloat162float(h2.x),
            v[2*q + 1] - __bfloat162float(h2.y));
        lw[q] = *reinterpret_cast<uint32_t*>(&l2);
    }
    hi[j] = make_uint4(hw[0], hw[1], hw[2], hw[3]);
    lo[j] = make_uint4(lw[0], lw[1], lw[2], lw[3]);
}

// ---------------------------------------------------------------------------
// Split-bf16 HMMA GEMM with mbarrier (barrier-free) pipeline. (R15-best)
// BM=128, BN=128, BK=32. 8 warps (2x4), each 64x32 tile. 2 CTAs/SM.
//   mode 0: split C into bf16 hi/lo head-major q/k/v (q pre-scaled)
//   mode 1: C + bias -> out (fp32, row-major)
// ---------------------------------------------------------------------------
#define BMm 128
#define BNn 128
#define BKk 32
#define NKI (En/BKk)            // 32
#define OFF_ALO  8192           // 128*64
#define OFF_BHI 16384
#define OFF_BLO 24576
#define STAGEB  32768
#define GEMM_SMEM (3*STAGEB + 128)   // slots + 6 mbarriers

__global__ __launch_bounds__(256, 2) void gemm_split_kernel(
    const __nv_bfloat16* __restrict__ Ahi, const __nv_bfloat16* __restrict__ Alo,
    const __nv_bfloat16* __restrict__ Bhi, const __nv_bfloat16* __restrict__ Blo,
    float* __restrict__ outp, const float* __restrict__ bias, int mode)
{
    extern __shared__ char dsm[];
    const uint32_t sb = smem_u32(dsm);
    const uint32_t FULLB  = sb + 3*STAGEB;       // 3 x 8B
    const uint32_t EMPTYB = sb + 3*STAGEB + 24;  // 3 x 8B
    const int tid = threadIdx.x;
    const int wid = tid >> 5, lane = tid & 31;
    const int wy = wid & 1, wx = wid >> 1;       // warp tile: (wy*64, wx*32)
    const int t0 = blockIdx.y * BMm, f0 = blockIdx.x * BNn;

    if (tid == 0) {
        #pragma unroll
        for (int s = 0; s < 3; s++) {
            MBAR_INIT(FULLB  + s*8, 256);
            MBAR_INIT(EMPTYB + s*8, 256);
        }
    }
    __syncthreads();   // only block-wide barrier in the kernel

    #define LOAD_STAGE(ki, s) do {                                            \
        uint32_t base_ = sb + (uint32_t)(s)*STAGEB;                           \
        int kofs_ = (ki)*BKk;                                                 \
        _Pragma("unroll")                                                     \
        for (int jj = 0; jj < 2; jj++) {                                      \
            int c_ = tid + jj*256;                                            \
            uint32_t row_ = (uint32_t)(c_ >> 2), ch_ = (uint32_t)(c_ & 3);    \
            uint32_t so_ = gsw(row_, ch_*16u);                                \
            size_t ga_ = (size_t)(t0 + (int)row_)*En + kofs_ + (int)ch_*8;    \
            size_t gb_ = (size_t)(f0 + (int)row_)*En + kofs_ + (int)ch_*8;    \
            ldgsts16_ca(base_ + so_,           Ahi + ga_);                    \
            ldgsts16_ca(base_ + OFF_ALO + so_, Alo + ga_);                    \
            ldgsts16(base_ + OFF_BHI + so_, Bhi + gb_);                       \
            ldgsts16(base_ + OFF_BLO + so_, Blo + gb_);                       \
        }                                                                     \
    } while (0)

    float acc[4][4][4] = {};   // [mi][nj][frag]

    // prologue: stages 0,1 (slots 0,1 are virgin — no empty wait)
    LOAD_STAGE(0, 0);
    CP_ASYNC_ARRIVE(FULLB + 0);
    LOAD_STAGE(1, 1);
    CP_ASYNC_ARRIVE(FULLB + 8);

    int slot = 0;
    for (int i = 0; i < NKI; i++) {
        // consume: wait stage i resident (parity = (i/3)&1)
        MBAR_WAIT(FULLB + slot*8, (uint32_t)((i/3) & 1));

        const uint32_t base = sb + (uint32_t)slot*STAGEB;
        const uint32_t lrow = lane & 15;
        const uint32_t lcol = (lane >> 4) << 4;

        #pragma unroll
        for (int kk = 0; kk < 2; kk++) {
            const uint32_t coff = (uint32_t)kk*32 + lcol;
            uint32_t ah[4][4], al[4][4];
            #pragma unroll
            for (int mi = 0; mi < 4; mi++) {
                uint32_t r = (uint32_t)(wy*64 + mi*16) + lrow;
                uint32_t addr = base + gsw(r, coff);
                LDSM_X4(ah[mi][0], ah[mi][1], ah[mi][2], ah[mi][3], addr);
                LDSM_X4(al[mi][0], al[mi][1], al[mi][2], al[mi][3], addr + OFF_ALO);
            }
            uint32_t bh[4][2], bl[4][2];
            #pragma unroll
            for (int pj = 0; pj < 2; pj++) {
                uint32_t r = (uint32_t)(wx*32 + pj*16) + lrow;
                uint32_t addr = base + OFF_BHI + gsw(r, coff);
                uint32_t r0, r1, r2, r3;
                LDSM_X4(r0, r1, r2, r3, addr);
                bh[2*pj][0] = r0; bh[2*pj+1][0] = r1;
                bh[2*pj][1] = r2; bh[2*pj+1][1] = r3;
                LDSM_X4(r0, r1, r2, r3, addr + (OFF_BLO - OFF_BHI));
                bl[2*pj][0] = r0; bl[2*pj+1][0] = r1;
                bl[2*pj][1] = r2; bl[2*pj+1][1] = r3;
            }
            if (kk == 1) MBAR_ARRIVE(EMPTYB + slot*8);  // all reads of slot issued
            #pragma unroll
            for (int mi = 0; mi < 4; mi++)
                #pragma unroll
                for (int nj = 0; nj < 4; nj++)
                    mma16816(acc[mi][nj], ah[mi], bh[nj][0], bh[nj][1]);
            #pragma unroll
            for (int mi = 0; mi < 4; mi++)
                #pragma unroll
                for (int nj = 0; nj < 4; nj++)
                    mma16816(acc[mi][nj], ah[mi], bl[nj][0], bl[nj][1]);
            #pragma unroll
            for (int mi = 0; mi < 4; mi++)
                #pragma unroll
                for (int nj = 0; nj < 4; nj++)
                    mma16816(acc[mi][nj], al[mi], bh[nj][0], bh[nj][1]);
        }

        // produce stage i+2 into slot (i+2)%3
        if (i + 2 < NKI) {
            int st = i + 2;
            int ls = slot + 2; if (ls >= 3) ls -= 3;
            int m = st / 3;
            if (m >= 1) MBAR_WAIT(EMPTYB + ls*8, (uint32_t)((m - 1) & 1));
            LOAD_STAGE(st, ls);
            CP_ASYNC_ARRIVE(FULLB + ls*8);
        }

        if (++slot == 3) slot = 0;
    }

    // ---------------- epilogue ----------------------------------------------
    const int mrow = lane >> 2;
    const int ncol = (lane & 3) * 2;

    #pragma unroll
    for (int mi = 0; mi < 4; mi++) {
        #pragma unroll
        for (int half = 0; half < 2; half++) {
            int t = t0 + wy*64 + mi*16 + mrow + half*8;
            #pragma unroll
            for (int nj = 0; nj < 4; nj++) {
                int f = f0 + wx*32 + nj*8 + ncol;
                float v0 = acc[mi][nj][half*2 + 0];
                float v1 = acc[mi][nj][half*2 + 1];
                if (mode == 0) {
                    int bidx = t >> 11, sidx = t & 2047;
                    int hh = f / 192;
                    int c = f - hh*192;
                    int kind = c >> 6, d = c & 63;
                    if (kind == 0) { v0 *= QSCALE; v1 *= QSCALE; }
                    __nv_bfloat16* hp = (kind == 0) ? g_qh : ((kind == 1) ? g_kh : g_vh);
                    __nv_bfloat16* lp = (kind == 0) ? g_ql : ((kind == 1) ? g_kl : g_vl);
                    size_t idx = (((size_t)(bidx*Hn + hh))*Sn + sidx)*HDn + d;
                    __nv_bfloat162 h2 = __floats2bfloat162_rn(v0, v1);
                    __nv_bfloat162 l2 = __floats2bfloat162_rn(
                        v0 - __bfloat162float(h2.x), v1 - __bfloat162float(h2.y));
                    *(__nv_bfloat162*)(hp + idx) = h2;
                    *(__nv_bfloat162*)(lp + idx) = l2;
                } else {
                    float2* p = (float2*)&outp[(size_t)t*En + f];
                    *p = make_float2(v0 + bias[f], v1 + bias[f + 1]);
                }
            }
        }
    }
}

// ---------------------------------------------------------------------------
// Kernel 2: causal flash attention (R15-proven), split-bf16 HMMA.
// 64 q-rows per CTA (4 warps, 128 threads), 3-slot swizzled KV ring,
// barrier-free mainloop, 2 CTAs/SM, qt longest-first.
// ---------------------------------------------------------------------------
#define A_QH 0
#define A_QL 8192               // 64 rows x 128B
#define A_ST0 16384
#define A_KH 0
#define A_KL 8192
#define A_VH 16384
#define A_VL 24576
#define A_STAGE 32768
#define ATTN_SMEM (A_ST0 + 3*A_STAGE + 128)   // 114816 (+6 mbarriers)

__global__ __launch_bounds__(128, 2) void attn_mma_kernel()
{
    extern __shared__ char dsm[];
    const uint32_t sb = smem_u32(dsm);
    const uint32_t FULLB  = sb + A_ST0 + 3*A_STAGE;       // 3 x 8B
    const uint32_t EMPTYB = sb + A_ST0 + 3*A_STAGE + 24;  // 3 x 8B
    const int tid = threadIdx.x;
    const int wid = tid >> 5, lane = tid & 31;   // wid 0..3
    const int qt = gridDim.x - 1 - blockIdx.x;   // longest-first (qt 0..31)
    const int bh = blockIdx.y;
    const int q0 = qt * 64;
    const size_t gbase = (size_t)bh * Sn * HDn;
    const int nk = qt + 1;                       // kv tiles (>=1)

    if (tid == 0) {
        #pragma unroll
        for (int s = 0; s < 3; s++) {
            MBAR_INIT(FULLB  + s*8, 128);
            MBAR_INIT(EMPTYB + s*8, 128);
        }
    }
    __syncthreads();   // only block barrier (covers mbarrier init)

    #define LOAD_KV(kt_, s_) do {                                             \
        uint32_t st_ = sb + A_ST0 + (uint32_t)(s_)*A_STAGE;                   \
        int kv_ = (kt_)*64;                                                   \
        _Pragma("unroll")                                                     \
        for (int j_ = 0; j_ < 4; j_++) {                                      \
            int c_ = tid + j_*128;                                            \
            uint32_t row_ = (uint32_t)(c_ >> 3), ch_ = (uint32_t)(c_ & 7);    \
            uint32_t so_ = asw(row_, ch_*16u);                                \
            size_t go_ = gbase + (size_t)(kv_ + (int)row_)*HDn + (int)ch_*8;  \
            ldgsts16(st_ + A_KH + so_, g_kh + go_);                           \
            ldgsts16(st_ + A_KL + so_, g_kl + go_);                           \
            ldgsts16(st_ + A_VH + so_, g_vh + go_);                           \
            ldgsts16(st_ + A_VL + so_, g_vl + go_);                           \
        } } while (0)

    // prologue: Q + KV0 tracked by FULL0 (noinc covers Q loads too); KV1 -> FULL1
    #pragma unroll
    for (int j = 0; j < 4; j++) {
        int c = tid + j*128;
        uint32_t row = (uint32_t)(c >> 3), ch = (uint32_t)(c & 7);
        uint32_t so = asw(row, ch*16u);
        size_t go = gbase + (size_t)(q0 + (int)row)*HDn + (int)ch*8;
        ldgsts16(sb + A_QH + so, g_qh + go);
        ldgsts16(sb + A_QL + so, g_ql + go);
    }
    LOAD_KV(0, 0);
    CP_ASYNC_ARRIVE(FULLB + 0);
    if (nk > 1) {
        LOAD_KV(1, 1);
        CP_ASYNC_ARRIVE(FULLB + 8);
    }

    // wait KV0 (and Q) resident, then grab Q fragments
    MBAR_WAIT(FULLB + 0, 0u);
    uint32_t qh_[4][4], ql_[4][4];
    {
        uint32_t r_ = (uint32_t)(wid*16 + (lane & 15));
        uint32_t cb = (uint32_t)((lane >> 4) << 4);
        #pragma unroll
        for (int kk = 0; kk < 4; kk++) {
            uint32_t addr = sb + A_QH + asw(r_, (uint32_t)kk*32 + cb);
            LDSM_X4(qh_[kk][0], qh_[kk][1], qh_[kk][2], qh_[kk][3], addr);
            LDSM_X4(ql_[kk][0], ql_[kk][1], ql_[kk][2], ql_[kk][3], addr + (A_QL - A_QH));
        }
    }

    float m0 = -INFINITY, m1 = -INFINITY, l0 = 0.f, l1 = 0.f;
    float acc[8][4] = {};

    for (int kt = 0; kt < nk; kt++) {
        const int slot = kt % 3;
        if (kt > 0) MBAR_WAIT(FULLB + slot*8, (uint32_t)((kt/3) & 1));

        const uint32_t st = sb + A_ST0 + (uint32_t)slot*A_STAGE;
        const int kv0 = kt * 64;

        // ---- S = Q @ K^T (3-term split, term-outer) ----
        float s[8][4] = {};
        {
            uint32_t r_ = (uint32_t)(lane & 15);
            uint32_t cb = (uint32_t)((lane >> 4) << 4);
            #pragma unroll
            for (int kk = 0; kk < 4; kk++) {
                uint32_t kh[8][2], kl[8][2];
                #pragma unroll
                for (int pj = 0; pj < 4; pj++) {
                    uint32_t addr = st + A_KH
                                  + asw((uint32_t)(pj*16) + r_, (uint32_t)kk*32 + cb);
                    uint32_t r0, r1, r2, r3;
                    LDSM_X4(r0, r1, r2, r3, addr);
                    kh[2*pj][0]=r0; kh[2*pj][1]=r2; kh[2*pj+1][0]=r1; kh[2*pj+1][1]=r3;
                    LDSM_X4(r0, r1, r2, r3, addr + (A_KL - A_KH));
                    kl[2*pj][0]=r0; kl[2*pj][1]=r2; kl[2*pj+1][0]=r1; kl[2*pj+1][1]=r3;
                }
                #pragma unroll
                for (int nj = 0; nj < 8; nj++)
                    mma16816(s[nj], qh_[kk], kh[nj][0], kh[nj][1]);
                #pragma unroll
                for (int nj = 0; nj < 8; nj++)
                    mma16816(s[nj], qh_[kk], kl[nj][0], kl[nj][1]);
                #pragma unroll
                for (int nj = 0; nj < 8; nj++)
                    mma16816(s[nj], ql_[kk], kh[nj][0], kh[nj][1]);
            }
        }

        // ---- causal mask (only diagonal tile needs it: kt == qt) ----
        const int rbase = q0 + wid*16 + (lane >> 2);
        if (kv0 + 63 > q0 + wid*16) {
            #pragma unroll
            for (int nj = 0; nj < 8; nj++)
                #pragma unroll
                for (int i = 0; i < 4; i++) {
                    int col = kv0 + nj*8 + (lane & 3)*2 + (i & 1);
                    int row = rbase + (i >> 1)*8;
                    if (col > row) s[nj][i] = -INFINITY;
                }
        }

        // ---- online softmax (exp2 domain) ----
        float mx0 = -INFINITY, mx1 = -INFINITY;
        #pragma unroll
        for (int nj = 0; nj < 8; nj++) {
            mx0 = fmaxf(mx0, fmaxf(s[nj][0], s[nj][1]));
            mx1 = fmaxf(mx1, fmaxf(s[nj][2], s[nj][3]));
        }
        mx0 = fmaxf(mx0, __shfl_xor_sync(0xffffffffu, mx0, 1));
        mx0 = fmaxf(mx0, __shfl_xor_sync(0xffffffffu, mx0, 2));
        mx1 = fmaxf(mx1, __shfl_xor_sync(0xffffffffu, mx1, 1));
        mx1 = fmaxf(mx1, __shfl_xor_sync(0xffffffffu, mx1, 2));
        float mn0 = fmaxf(m0, mx0), mn1 = fmaxf(m1, mx1);
        float al0 = ex2f(m0 - mn0), al1 = ex2f(m1 - mn1);
        m0 = mn0; m1 = mn1;
        float rs0 = 0.f, rs1 = 0.f;
        #pragma unroll
        for (int nj = 0; nj < 8; nj++) {
            float p0 = ex2f(s[nj][0] - mn0), p1 = ex2f(s[nj][1] - mn0);
            float p2 = ex2f(s[nj][2] - mn1), p3 = ex2f(s[nj][3] - mn1);
            s[nj][0] = p0; s[nj][1] = p1; s[nj][2] = p2; s[nj][3] = p3;
            rs0 += p0 + p1; rs1 += p2 + p3;
        }
        rs0 += __shfl_xor_sync(0xffffffffu, rs0, 1);
        rs0 += __shfl_xor_sync(0xffffffffu, rs0, 2);
        rs1 += __shfl_xor_sync(0xffffffffu, rs1, 1);
        rs1 += __shfl_xor_sync(0xffffffffu, rs1, 2);
        l0 = l0*al0 + rs0;
        l1 = l1*al1 + rs1;
        #pragma unroll
        for (int nj = 0; nj < 8; nj++) {
            acc[nj][0] *= al0; acc[nj][1] *= al0;
            acc[nj][2] *= al1; acc[nj][3] *= al1;
        }

        // ---- O += P @ V (3-term split, term-outer; V via ldmatrix.trans) ----
        {
            uint32_t rr = (uint32_t)(((lane >> 4) << 3) + (lane & 7));
            uint32_t cb = (uint32_t)(((lane >> 3) & 1) << 4);
            #pragma unroll
            for (int kk2 = 0; kk2 < 4; kk2++) {
                uint32_t pah[4], pal[4];
                #pragma unroll
                for (int tp = 0; tp < 2; tp++) {
                    int t_ = 2*kk2 + tp;
                    float p0 = s[t_][0], p1 = s[t_][1], p2 = s[t_][2], p3 = s[t_][3];
                    __nv_bfloat162 h01 = __floats2bfloat162_rn(p0, p1);
                    __nv_bfloat162 h23 = __floats2bfloat162_rn(p2, p3);
                    pah[2*tp+0] = *reinterpret_cast<uint32_t*>(&h01);
                    pah[2*tp+1] = *reinterpret_cast<uint32_t*>(&h23);
                    pal[2*tp+0] = pack_bf2(p0 - __bfloat162float(h01.x),
                                           p1 - __bfloat162float(h01.y));
                    pal[2*tp+1] = pack_bf2(p2 - __bfloat162float(h23.x),
                                           p3 - __bfloat162float(h23.y));
                }
                uint32_t bvh[8][2], bvl[8][2];
                #pragma unroll
                for (int dj = 0; dj < 4; dj++) {
                    uint32_t addr = st + A_VH
                                  + asw((uint32_t)(kk2*16) + rr, (uint32_t)dj*32 + cb);
                    uint32_t r0, r1, r2, r3;
                    LDSM_X4_T(r0, r1, r2, r3, addr);
                    bvh[2*dj][0]=r0; bvh[2*dj][1]=r2; bvh[2*dj+1][0]=r1; bvh[2*dj+1][1]=r3;
                    LDSM_X4_T(r0, r1, r2, r3, addr + (A_VL - A_VH));
                    bvl[2*dj][0]=r0; bvl[2*dj][1]=r2; bvl[2*dj+1][0]=r1; bvl[2*dj+1][1]=r3;
                }
                #pragma unroll
                for (int nj = 0; nj < 8; nj++)
                    mma16816(acc[nj], pah, bvh[nj][0], bvh[nj][1]);
                #pragma unroll
                for (int nj = 0; nj < 8; nj++)
                    mma16816(acc[nj], pah, bvl[nj][0], bvl[nj][1]);
                #pragma unroll
                for (int nj = 0; nj < 8; nj++)
                    mma16816(acc[nj], pal, bvh[nj][0], bvh[nj][1]);
            }
        }

        // all reads of this slot issued -> release
        MBAR_ARRIVE(EMPTYB + slot*8);

        // produce kt+2 into slot (kt+2)%3
        if (kt + 2 < nk) {
            int stg = kt + 2;
            int ls = stg % 3;
            int m = stg / 3;
            if (m >= 1) MBAR_WAIT(EMPTYB + ls*8, (uint32_t)((m - 1) & 1));
            LOAD_KV(stg, ls);
            CP_ASYNC_ARRIVE(FULLB + ls*8);
        }
    }

    // ---- epilogue: normalize, write bf16 hi/lo for proj GEMM ----
    float inv0 = 1.f / l0, inv1 = 1.f / l1;
    const int b = bh >> 4, h = bh & 15;
    const int r0_ = q0 + wid*16 + (lane >> 2);
    #pragma unroll
    for (int nj = 0; nj < 8; nj++) {
        int d = nj*8 + (lane & 3)*2;
        size_t i0 = (size_t)(b*Sn + r0_)*En + h*HDn + d;
        size_t i1 = i0 + (size_t)8*En;
        float o0 = acc[nj][0]*inv0, o1 = acc[nj][1]*inv0;
        float o2 = acc[nj][2]*inv1, o3 = acc[nj][3]*inv1;
        __nv_bfloat162 h01 = __floats2bfloat162_rn(o0, o1);
        __nv_bfloat162 l01 = __floats2bfloat162_rn(o0 - __bfloat162float(h01.x),
                                                   o1 - __bfloat162float(h01.y));
        __nv_bfloat162 h23 = __floats2bfloat162_rn(o2, o3);
        __nv_bfloat162 l23 = __floats2bfloat162_rn(o2 - __bfloat162float(h23.x),
                                                   o3 - __bfloat162float(h23.y));
        *(__nv_bfloat162*)(g_att_hi + i0) = h01;
        *(__nv_bfloat162*)(g_att_lo + i0) = l01;
        *(__nv_bfloat162*)(g_att_hi + i1) = h23;
        *(__nv_bfloat162*)(g_att_lo + i1) = l23;
    }
}

// ---------------------------------------------------------------------------
extern "C" void kernel_launch(void* const* d_in, const int* in_sizes, int n_in,
                              void* d_out, int out_size)
{
    const float* x      = (const float*)d_in[0];
    const float* w_qkv  = (const float*)d_in[1];
    const float* w_proj = (const float*)d_in[2];
    const float* b_proj = (const float*)d_in[3];
    float* out = (float*)d_out;

    cudaFuncSetAttribute(gemm_split_kernel,
                         cudaFuncAttributeMaxDynamicSharedMemorySize, GEMM_SMEM);
    cudaFuncSetAttribute(attn_mma_kernel,
                         cudaFuncAttributeMaxDynamicSharedMemorySize, ATTN_SMEM);

    __nv_bfloat16 *xhi, *xlo, *wqhi, *wqlo, *wphi, *wplo, *athi, *atlo;
    cudaGetSymbolAddress((void**)&xhi,  g_x_hi);
    cudaGetSymbolAddress((void**)&xlo,  g_x_lo);
    cudaGetSymbolAddress((void**)&wqhi, g_wq_hi);
    cudaGetSymbolAddress((void**)&wqlo, g_wq_lo);
    cudaGetSymbolAddress((void**)&wphi, g_wp_hi);
    cudaGetSymbolAddress((void**)&wplo, g_wp_lo);
    cudaGetSymbolAddress((void**)&athi, g_att_hi);
    cudaGetSymbolAddress((void**)&atlo, g_att_lo);

    // fused fp32 -> bf16 hi/lo split (16B stores), one launch
    split_all_kernel<<<(N8_ALL + 255)/256, 256>>>(
        (const float4*)x, (const float4*)w_qkv, (const float4*)w_proj);

    // QKV GEMM (split-bf16 HMMA, mbarrier pipeline) -> bf16 hi/lo Q/K/V
    gemm_split_kernel<<<dim3(F1n/BNn, Tn/BMm), 256, GEMM_SMEM>>>(
        xhi, xlo, wqhi, wqlo, nullptr, nullptr, 0);

    // causal flash attention (split-bf16 HMMA, 3-slot mbarrier KV ring)
    attn_mma_kernel<<<dim3(Sn/64, Bn*Hn), 128, ATTN_SMEM>>>();

    // output projection (split-bf16 HMMA, mbarrier pipeline) + bias
    gemm_split_kernel<<<dim3(En/BNn, Tn/BMm), 256, GEMM_SMEM>>>(
        athi, atlo, wphi, wplo, out, b_proj, 1);
}